// round 7
// baseline (speedup 1.0000x reference)
#include <cuda_runtime.h>
#include <cstdint>

#define NN 50000
#define NE 600000
#define NG 64

// ---------------- scratch (no allocations allowed) ----------------
__device__ float g_agg[(size_t)NN * 128];
__device__ float g_h  [(size_t)NN * 128];
__device__ float g_wt[4][128 * 128];   // tf32-rounded weights
__device__ float g_pool[NG * 128];
__device__ float g_cnt[NG];
__device__ int   g_is64;
// CSR scratch
__device__ int    g_cntE[NN];
__device__ int    g_rowptr[NN + 1];
__device__ int    g_wofs[NN];
__device__ float4 g_erec[NE];      // {src(bitcast), a0, a1, a2} per dst-sorted slot
__device__ int    g_bsum[128];

// ---------------- helpers ----------------
__device__ __forceinline__ void red_add_v4(float* addr, float a, float b, float c, float d) {
    asm volatile("red.global.add.v4.f32 [%0], {%1,%2,%3,%4};"
                 :: "l"(addr), "f"(a), "f"(b), "f"(c), "f"(d) : "memory");
}
__device__ __forceinline__ long long load_idx(const void* p, long long i, int is64) {
    if (is64) return ((const long long*)p)[i];
    return (long long)((const int*)p)[i];
}
__device__ __forceinline__ uint32_t f2tf32(float x) {
    uint32_t r;
    asm("cvt.rna.tf32.f32 %0, %1;" : "=r"(r) : "f"(x));
    return r;
}
__device__ __forceinline__ float f2tf32f(float x) { return __uint_as_float(f2tf32(x)); }
__device__ __forceinline__ uint32_t smem_u32(const void* p) {
    uint32_t a;
    asm("{ .reg .u64 t; cvta.to.shared.u64 t, %1; cvt.u32.u64 %0, t; }" : "=r"(a) : "l"(p));
    return a;
}
__device__ __forceinline__ void cpa16(uint32_t dst, const void* src, uint32_t sz) {
    asm volatile("cp.async.ca.shared.global [%0], [%1], 16, %2;"
                 :: "r"(dst), "l"(src), "r"(sz) : "memory");
}
#define CPA_COMMIT() asm volatile("cp.async.commit_group;" ::: "memory")
#define CPA_WAIT0()  asm volatile("cp.async.wait_group 0;" ::: "memory")

__device__ __forceinline__ void mma16n8k8(float* c, const uint32_t* a, uint32_t b0, uint32_t b1) {
    asm volatile("mma.sync.aligned.m16n8k8.row.col.f32.tf32.tf32.f32 "
                 "{%0,%1,%2,%3}, {%4,%5,%6,%7}, {%8,%9}, {%0,%1,%2,%3};"
                 : "+f"(c[0]), "+f"(c[1]), "+f"(c[2]), "+f"(c[3])
                 : "r"(a[0]), "r"(a[1]), "r"(a[2]), "r"(a[3]), "r"(b0), "r"(b1));
}

__global__ void detect_kernel(const int* ei32) {
    int v = ei32[2 * threadIdx.x + 1] | ei32[2 * (threadIdx.x + 32) + 1];
    unsigned b = __ballot_sync(0xffffffffu, v != 0);
    if (threadIdx.x == 0) g_is64 = (b == 0) ? 1 : 0;
}
__global__ void zero_kernel(float* p, long long n4) {
    long long i = (long long)blockIdx.x * blockDim.x + threadIdx.x;
    if (i < n4) ((float4*)p)[i] = make_float4(0.f, 0.f, 0.f, 0.f);
}
// round weights to tf32 once
__global__ void wprep_kernel(const float* __restrict__ src, float* __restrict__ dst, int n) {
    int i = blockIdx.x * blockDim.x + threadIdx.x;
    if (i < n) dst[i] = f2tf32f(src[i]);
}

// ---------------- CSR build (dst-binned) ----------------
__global__ void hist_kernel(const void* __restrict__ ei, int* __restrict__ cnt) {
    long long e = (long long)blockIdx.x * blockDim.x + threadIdx.x;
    if (e < NE) {
        long long dst = load_idx(ei, NE + e, g_is64);
        atomicAdd(&cnt[dst], 1);
    }
}
__global__ void scan1_kernel(const int* __restrict__ cnt, int* __restrict__ rowptr,
                             int* __restrict__ bsum) {
    __shared__ int wsum[16];
    int tid = threadIdx.x, lane = tid & 31, wid = tid >> 5;
    int i = blockIdx.x * 512 + tid;
    int v = (i < NN) ? cnt[i] : 0;
    int s = v;
#pragma unroll
    for (int ofs = 1; ofs < 32; ofs <<= 1) {
        int t = __shfl_up_sync(0xffffffffu, s, ofs);
        if (lane >= ofs) s += t;
    }
    if (lane == 31) wsum[wid] = s;
    __syncthreads();
    if (wid == 0 && lane < 16) {
        int w = wsum[lane];
        int ws = w;
#pragma unroll
        for (int ofs = 1; ofs < 16; ofs <<= 1) {
            int t = __shfl_up_sync(0xffffu, ws, ofs);
            if (lane >= ofs) ws += t;
        }
        wsum[lane] = ws - w;   // exclusive warp offsets
    }
    __syncthreads();
    int incl = s + wsum[wid];
    if (i < NN) rowptr[i] = incl - v;
    if (tid == 511) bsum[blockIdx.x] = incl;
}
__global__ void scan2_kernel(int* __restrict__ bsum, int nb) {
    __shared__ int s[128];
    int tid = threadIdx.x;
    int v = (tid < nb) ? bsum[tid] : 0;
    s[tid] = v;
    __syncthreads();
    for (int ofs = 1; ofs < 128; ofs <<= 1) {
        int t = (tid >= ofs) ? s[tid - ofs] : 0;
        __syncthreads();
        s[tid] += t;
        __syncthreads();
    }
    if (tid < nb) bsum[tid] = s[tid] - v;
}
__global__ void scan3_kernel(int* __restrict__ rowptr, const int* __restrict__ bsum,
                             int* __restrict__ wofs) {
    int i = blockIdx.x * blockDim.x + threadIdx.x;
    if (i < NN) {
        int r = rowptr[i] + bsum[i >> 9];
        rowptr[i] = r;
        wofs[i] = r;
    }
    if (i == 0) rowptr[NN] = NE;
}
__global__ void scatter_kernel(const void* __restrict__ ei, const float* __restrict__ attr,
                               int* __restrict__ wofs, float4* __restrict__ rec) {
    long long e = (long long)blockIdx.x * blockDim.x + threadIdx.x;
    if (e < NE) {
        int is64 = g_is64;
        long long dst = load_idx(ei, NE + e, is64);
        int src = (int)load_idx(ei, e, is64);
        int pos = atomicAdd(&wofs[dst], 1);
        float4 r;
        r.x = __int_as_float(src);
        r.y = __ldg(&attr[e * 3 + 0]);
        r.z = __ldg(&attr[e * 3 + 1]);
        r.w = __ldg(&attr[e * 3 + 2]);
        rec[pos] = r;
    }
}

// ---------------- gather aggregation: one warp per node ----------------
// out[n] = tf32( x[n] + sum_{e: dst(e)=n} relu(x[src(e)] + attr(e) @ ew + eb) )
template <int CH>
__global__ void agg_kernel(const float* __restrict__ x, const float4* __restrict__ recs,
                           const float* __restrict__ ew, const float* __restrict__ eb,
                           const int* __restrict__ rowptr, float* __restrict__ out) {
    const int VPL = CH / 32;
    int warp = (int)(((long long)blockIdx.x * blockDim.x + threadIdx.x) >> 5);
    int lane = threadIdx.x & 31;
    if (warp >= NN) return;
    int c0 = lane * VPL;
    float ew0[VPL], ew1[VPL], ew2[VPL], ebv[VPL], acc[VPL];
#pragma unroll
    for (int j = 0; j < VPL; j++) {
        ew0[j] = __ldg(&ew[c0 + j]);
        ew1[j] = __ldg(&ew[CH + c0 + j]);
        ew2[j] = __ldg(&ew[2 * CH + c0 + j]);
        ebv[j] = __ldg(&eb[c0 + j]);
        acc[j] = 0.f;
    }
    int beg = __ldg(&rowptr[warp]);
    int end = __ldg(&rowptr[warp + 1]);
    int p = beg;
    for (; p + 3 < end; p += 4) {
        float4 r[4];
        float xv[4][VPL];
#pragma unroll
        for (int u = 0; u < 4; u++) r[u] = __ldg(&recs[p + u]);
#pragma unroll
        for (int u = 0; u < 4; u++) {
            long long s = (long long)__float_as_int(r[u].x);
            if (VPL == 4) *(float4*)xv[u] = *(const float4*)&x[s * CH + c0];
            else          *(float2*)xv[u] = *(const float2*)&x[s * CH + c0];
        }
#pragma unroll
        for (int u = 0; u < 4; u++)
#pragma unroll
            for (int j = 0; j < VPL; j++) {
                float ev = ebv[j] + r[u].y * ew0[j] + r[u].z * ew1[j] + r[u].w * ew2[j];
                acc[j] += fmaxf(xv[u][j] + ev, 0.f);
            }
    }
    for (; p < end; p++) {
        float4 r0 = __ldg(&recs[p]);
        long long s0 = (long long)__float_as_int(r0.x);
        float x0[VPL];
        if (VPL == 4) *(float4*)x0 = *(const float4*)&x[s0 * CH + c0];
        else          *(float2*)x0 = *(const float2*)&x[s0 * CH + c0];
#pragma unroll
        for (int j = 0; j < VPL; j++) {
            float e0 = ebv[j] + r0.y * ew0[j] + r0.z * ew1[j] + r0.w * ew2[j];
            acc[j] += fmaxf(x0[j] + e0, 0.f);
        }
    }
    float sv[VPL];
    if (VPL == 4) *(float4*)sv = *(const float4*)&x[(long long)warp * CH + c0];
    else          *(float2*)sv = *(const float2*)&x[(long long)warp * CH + c0];
#pragma unroll
    for (int j = 0; j < VPL; j++) sv[j] = f2tf32f(sv[j] + acc[j]);
    if (VPL == 4) *(float4*)&out[(long long)warp * CH + c0] = *(float4*)sv;
    else          *(float2*)&out[(long long)warp * CH + c0] = *(float2*)sv;
}

// ---------------- fused 2-GEMM node MLP (tf32 mma.sync, cp.async pipelined) ----------------
// C = relu( relu(A @ W1 + b1) @ W2 + b2 )
// A and W are pre-rounded to tf32 values (HMMA truncation = identity).
// SMEM (words): As[2][128][20] @0 (5120) | Ws[2][16][136] @5120 (4352) | Mid[128][132] @9472 (16896)
template <int K1>
__global__ __launch_bounds__(256, 2) void fused_mlp_kernel(
    const float* __restrict__ A, const float* __restrict__ W1, const float* __restrict__ b1,
    const float* __restrict__ W2, const float* __restrict__ b2, float* __restrict__ C) {
    extern __shared__ uint32_t sm[];
    uint32_t* As  = sm;              // [buf][128][20]
    uint32_t* Ws  = sm + 5120;       // [buf][16][136]
    uint32_t (*Mid)[132] = (uint32_t(*)[132])(sm + 9472);

    const uint32_t sm_b = smem_u32(sm);
    const uint32_t as_b = sm_b;
    const uint32_t ws_b = sm_b + 5120 * 4;

    const int tid = threadIdx.x, lane = tid & 31, wid = tid >> 5;
    const int block_row = blockIdx.x * 128;
    const int rbase = (wid & 3) * 32;
    const int cbase = (wid >> 2) * 64;
    const int g4 = lane >> 2;
    const int t4 = lane & 3;

    // per-thread staging coords
    const int ar0 = tid >> 2, akc = (tid & 3) * 4;            // A chunk 0: rows 0..63
    const int ar1 = (tid + 256) >> 2;                          // A chunk 1: rows 64..127
    const int wr0 = tid >> 5, wcc = (tid & 31) * 4;            // W chunk 0: k 0..7
    const int wr1 = (tid + 256) >> 5;                          // W chunk 1: k 8..15
    const long long gr0 = block_row + ar0, gr1 = block_row + ar1;
    const uint32_t sz0 = (gr0 < NN) ? 16u : 0u, sz1 = (gr1 < NN) ? 16u : 0u;

    float acc[2][8][4];
#pragma unroll
    for (int i = 0; i < 2; i++)
#pragma unroll
        for (int j = 0; j < 8; j++)
#pragma unroll
            for (int q = 0; q < 4; q++) acc[i][j][q] = 0.f;

    // ---------- GEMM 1: acc = A @ W1 (double-buffered cp.async) ----------
    const int NB1 = K1 / 16;
    {
        // prologue: stage block 0 into buf 0
        cpa16(as_b + (ar0 * 20 + akc) * 4, &A[gr0 * K1 + akc], sz0);
        cpa16(as_b + (ar1 * 20 + akc) * 4, &A[gr1 * K1 + akc], sz1);
        cpa16(ws_b + (wr0 * 136 + wcc) * 4, &W1[(long long)wr0 * 128 + wcc], 16);
        cpa16(ws_b + (wr1 * 136 + wcc) * 4, &W1[(long long)wr1 * 128 + wcc], 16);
        CPA_COMMIT();
    }
    for (int kb = 0; kb < NB1; kb++) {
        CPA_WAIT0();
        __syncthreads();
        if (kb + 1 < NB1) {
            int k0 = (kb + 1) * 16;
            uint32_t ab = as_b + ((kb + 1) & 1) * 2560 * 4;
            uint32_t wb = ws_b + ((kb + 1) & 1) * 2176 * 4;
            cpa16(ab + (ar0 * 20 + akc) * 4, &A[gr0 * K1 + k0 + akc], sz0);
            cpa16(ab + (ar1 * 20 + akc) * 4, &A[gr1 * K1 + k0 + akc], sz1);
            cpa16(wb + (wr0 * 136 + wcc) * 4, &W1[(long long)(k0 + wr0) * 128 + wcc], 16);
            cpa16(wb + (wr1 * 136 + wcc) * 4, &W1[(long long)(k0 + wr1) * 128 + wcc], 16);
            CPA_COMMIT();
        }
        const uint32_t* Ab = As + (kb & 1) * 2560;
        const uint32_t* Wb = Ws + (kb & 1) * 2176;
#pragma unroll
        for (int ks = 0; ks < 2; ks++) {
            const int kk = ks * 8;
            uint32_t a[2][4];
#pragma unroll
            for (int i = 0; i < 2; i++) {
                int r = rbase + i * 16 + g4;
                a[i][0] = Ab[r * 20 + kk + t4];
                a[i][1] = Ab[(r + 8) * 20 + kk + t4];
                a[i][2] = Ab[r * 20 + kk + t4 + 4];
                a[i][3] = Ab[(r + 8) * 20 + kk + t4 + 4];
            }
#pragma unroll
            for (int j = 0; j < 8; j++) {
                int cn = cbase + j * 8 + g4;
                uint32_t b0 = Wb[(kk + t4) * 136 + cn];
                uint32_t b1 = Wb[(kk + t4 + 4) * 136 + cn];
#pragma unroll
                for (int i = 0; i < 2; i++) mma16n8k8(acc[i][j], a[i], b0, b1);
            }
        }
    }
    __syncthreads();
    // epilogue 1: Mid = tf32(relu(acc + b1))
#pragma unroll
    for (int j = 0; j < 8; j++) {
        int col = cbase + j * 8 + t4 * 2;
        float bx = __ldg(&b1[col]);
        float by = __ldg(&b1[col + 1]);
#pragma unroll
        for (int i = 0; i < 2; i++) {
            int r0 = rbase + i * 16 + g4;
            Mid[r0][col]         = f2tf32(fmaxf(acc[i][j][0] + bx, 0.f));
            Mid[r0][col + 1]     = f2tf32(fmaxf(acc[i][j][1] + by, 0.f));
            Mid[r0 + 8][col]     = f2tf32(fmaxf(acc[i][j][2] + bx, 0.f));
            Mid[r0 + 8][col + 1] = f2tf32(fmaxf(acc[i][j][3] + by, 0.f));
            acc[i][j][0] = 0.f; acc[i][j][1] = 0.f; acc[i][j][2] = 0.f; acc[i][j][3] = 0.f;
        }
    }
    __syncthreads();

    // ---------- GEMM 2: acc = Mid @ W2 (Mid resident; W double-buffered) ----------
    {
        cpa16(ws_b + (wr0 * 136 + wcc) * 4, &W2[(long long)wr0 * 128 + wcc], 16);
        cpa16(ws_b + (wr1 * 136 + wcc) * 4, &W2[(long long)wr1 * 128 + wcc], 16);
        CPA_COMMIT();
    }
    for (int kb = 0; kb < 8; kb++) {
        CPA_WAIT0();
        __syncthreads();
        if (kb + 1 < 8) {
            int k0 = (kb + 1) * 16;
            uint32_t wb = ws_b + ((kb + 1) & 1) * 2176 * 4;
            cpa16(wb + (wr0 * 136 + wcc) * 4, &W2[(long long)(k0 + wr0) * 128 + wcc], 16);
            cpa16(wb + (wr1 * 136 + wcc) * 4, &W2[(long long)(k0 + wr1) * 128 + wcc], 16);
            CPA_COMMIT();
        }
        const uint32_t* Wb = Ws + (kb & 1) * 2176;
        const int k0 = kb * 16;
#pragma unroll
        for (int ks = 0; ks < 2; ks++) {
            const int kk = ks * 8;
            uint32_t a[2][4];
#pragma unroll
            for (int i = 0; i < 2; i++) {
                int r = rbase + i * 16 + g4;
                a[i][0] = Mid[r][k0 + kk + t4];
                a[i][1] = Mid[r + 8][k0 + kk + t4];
                a[i][2] = Mid[r][k0 + kk + t4 + 4];
                a[i][3] = Mid[r + 8][k0 + kk + t4 + 4];
            }
#pragma unroll
            for (int j = 0; j < 8; j++) {
                int cn = cbase + j * 8 + g4;
                uint32_t b0 = Wb[(kk + t4) * 136 + cn];
                uint32_t b1 = Wb[(kk + t4 + 4) * 136 + cn];
#pragma unroll
                for (int i = 0; i < 2; i++) mma16n8k8(acc[i][j], a[i], b0, b1);
            }
        }
    }
    // epilogue 2: C = relu(acc + b2)
#pragma unroll
    for (int j = 0; j < 8; j++) {
        int col = cbase + j * 8 + t4 * 2;
        float bx = __ldg(&b2[col]);
        float by = __ldg(&b2[col + 1]);
#pragma unroll
        for (int i = 0; i < 2; i++) {
            int r0 = block_row + rbase + i * 16 + g4;
            if (r0 < NN) {
                float2 o0 = make_float2(fmaxf(acc[i][j][0] + bx, 0.f),
                                        fmaxf(acc[i][j][1] + by, 0.f));
                *(float2*)&C[(long long)r0 * 128 + col] = o0;
            }
            if (r0 + 8 < NN) {
                float2 o1 = make_float2(fmaxf(acc[i][j][2] + bx, 0.f),
                                        fmaxf(acc[i][j][3] + by, 0.f));
                *(float2*)&C[(long long)(r0 + 8) * 128 + col] = o1;
            }
        }
    }
}

// ---------------- global mean pool ----------------
__global__ void pool_kernel(const float* __restrict__ h, const void* __restrict__ batch,
                            float* __restrict__ pool, float* __restrict__ cnt) {
    long long idx = (long long)blockIdx.x * blockDim.x + threadIdx.x;
    if (idx >= (long long)NN * 32) return;
    long long n = idx >> 5;
    int c4 = (int)(idx & 31) * 4;
    long long g = load_idx(batch, n, g_is64);
    float4 v = *(const float4*)&h[n * 128 + c4];
    red_add_v4(&pool[g * 128 + c4], v.x, v.y, v.z, v.w);
    if (c4 == 0) atomicAdd(&cnt[g], 1.0f);
}
__global__ void finalize_kernel(const float* __restrict__ pool, const float* __restrict__ cnt,
                                float* __restrict__ out) {
    int i = blockIdx.x * blockDim.x + threadIdx.x;
    if (i < NG * 128) out[i] = pool[i] / fmaxf(cnt[i >> 7], 1.0f);
}

// ---------------- launch ----------------
extern "C" void kernel_launch(void* const* d_in, const int* in_sizes, int n_in,
                              void* d_out, int out_size) {
    const float* x     = (const float*)d_in[0];
    const void*  ei    = d_in[1];
    const float* attr  = (const float*)d_in[2];
    const void*  batch = d_in[3];
    const float* el1_w = (const float*)d_in[4];
    const float* el1_b = (const float*)d_in[5];
    const float* w1a   = (const float*)d_in[6];
    const float* b1a   = (const float*)d_in[7];
    const float* w1b   = (const float*)d_in[8];
    const float* b1b   = (const float*)d_in[9];
    const float* el2_w = (const float*)d_in[10];
    const float* el2_b = (const float*)d_in[11];
    const float* w2a   = (const float*)d_in[12];
    const float* b2a   = (const float*)d_in[13];
    const float* w2b   = (const float*)d_in[14];
    const float* b2b   = (const float*)d_in[15];
    float* out = (float*)d_out;

    float *agg, *h, *pool, *cnt, *wt;
    int *cntE, *rowptr, *wofs, *bsum;
    float4* erec;
    cudaGetSymbolAddress((void**)&agg,  g_agg);
    cudaGetSymbolAddress((void**)&h,    g_h);
    cudaGetSymbolAddress((void**)&pool, g_pool);
    cudaGetSymbolAddress((void**)&cnt,  g_cnt);
    cudaGetSymbolAddress((void**)&wt,   g_wt);
    cudaGetSymbolAddress((void**)&cntE,   g_cntE);
    cudaGetSymbolAddress((void**)&rowptr, g_rowptr);
    cudaGetSymbolAddress((void**)&wofs,   g_wofs);
    cudaGetSymbolAddress((void**)&erec,   g_erec);
    cudaGetSymbolAddress((void**)&bsum,   g_bsum);
    float* wt1a = wt;
    float* wt1b = wt + 128 * 128;
    float* wt2a = wt + 2 * 128 * 128;
    float* wt2b = wt + 3 * 128 * 128;

    const int SMF = (2 * 128 * 20 + 2 * 16 * 136 + 128 * 132) * 4;   // 105472 B
    cudaFuncSetAttribute(fused_mlp_kernel<64>,  cudaFuncAttributeMaxDynamicSharedMemorySize, SMF);
    cudaFuncSetAttribute(fused_mlp_kernel<128>, cudaFuncAttributeMaxDynamicSharedMemorySize, SMF);

    detect_kernel<<<1, 32>>>((const int*)ei);

    // pre-round weights to tf32
    wprep_kernel<<<(64 * 128 + 255) / 256, 256>>>(w1a, wt1a, 64 * 128);
    wprep_kernel<<<(128 * 128 + 255) / 256, 256>>>(w1b, wt1b, 128 * 128);
    wprep_kernel<<<(128 * 128 + 255) / 256, 256>>>(w2a, wt2a, 128 * 128);
    wprep_kernel<<<(128 * 128 + 255) / 256, 256>>>(w2b, wt2b, 128 * 128);

    // ---- CSR build (once; reused by both layers) ----
    const int NB = (NN + 511) / 512;
    zero_kernel<<<(NN / 4 + 255) / 256, 256>>>((float*)cntE, NN / 4);
    hist_kernel<<<(NE + 255) / 256, 256>>>(ei, cntE);
    scan1_kernel<<<NB, 512>>>(cntE, rowptr, bsum);
    scan2_kernel<<<1, 128>>>(bsum, NB);
    scan3_kernel<<<(NN + 255) / 256, 256>>>(rowptr, bsum, wofs);
    scatter_kernel<<<(NE + 255) / 256, 256>>>(ei, attr, wofs, erec);

    const int ggrid = (NN + 127) / 128;
    const int agrid = (int)(((long long)NN * 32 + 255) / 256);

    // ---- layer 1 ----
    agg_kernel<64><<<agrid, 256>>>(x, erec, el1_w, el1_b, rowptr, agg);
    fused_mlp_kernel<64><<<ggrid, 256, SMF>>>(agg, wt1a, b1a, wt1b, b1b, h);

    // ---- layer 2 ----
    agg_kernel<128><<<agrid, 256>>>(h, erec, el2_w, el2_b, rowptr, agg);
    fused_mlp_kernel<128><<<ggrid, 256, SMF>>>(agg, wt2a, b2a, wt2b, b2b, h);

    // ---- global mean pool ----
    zero_kernel<<<(NG * 128 / 4 + 255) / 256, 256>>>(pool, NG * 128 / 4);
    zero_kernel<<<1, 16>>>(cnt, NG / 4);
    {
        long long t = (long long)NN * 32;
        pool_kernel<<<(int)((t + 255) / 256), 256>>>(h, batch, pool, cnt);
    }
    finalize_kernel<<<(NG * 128 + 255) / 256, 256>>>(pool, cnt, out);
}